// round 4
// baseline (speedup 1.0000x reference)
#include <cuda_runtime.h>
#include <stdint.h>

#define NNODES_MAX 100000
#define F_IN 128
#define F4 32   // float4s per feature row

// ---- scratch (static __device__ globals; allocation-free) ----
__device__ int   g_deg[NNODES_MAX];
__device__ float g_dinv[NNODES_MAX];
__device__ float g_acc[(size_t)NNODES_MAX * F_IN];

// ---------------------------------------------------------------------------
// K0: deg[v] = 1 (self loop)
// ---------------------------------------------------------------------------
__global__ void k_init_deg(int n) {
    int v = blockIdx.x * blockDim.x + threadIdx.x;
    if (v < n) g_deg[v] = 1;
}

// ---------------------------------------------------------------------------
// K1: deg[col[e]] += 1 for every edge (int atomics, 4 edges/thread)
// ---------------------------------------------------------------------------
__global__ void k_count(const int* __restrict__ col, int E) {
    int i = blockIdx.x * blockDim.x + threadIdx.x;
    int base = i * 4;
    if (base + 3 < E) {
        int4 c = *reinterpret_cast<const int4*>(col + base);
        atomicAdd(&g_deg[c.x], 1);
        atomicAdd(&g_deg[c.y], 1);
        atomicAdd(&g_deg[c.z], 1);
        atomicAdd(&g_deg[c.w], 1);
    } else if (base < E) {
        for (int e = base; e < E; ++e) atomicAdd(&g_deg[col[e]], 1);
    }
}

// ---------------------------------------------------------------------------
// K2: dinv[v] = rsqrt(deg[v]);  acc[v][:] = x[v][:] * dinv[v]   (self-loop term)
// one thread per float4
// ---------------------------------------------------------------------------
__global__ void k_selfinit(const float* __restrict__ x, int n) {
    int idx = blockIdx.x * blockDim.x + threadIdx.x;
    if (idx >= n * F4) return;
    int v = idx >> 5;
    float dinv = rsqrtf((float)g_deg[v]);
    if ((idx & 31) == 0) g_dinv[v] = dinv;
    float4 xv = reinterpret_cast<const float4*>(x)[idx];
    float4 o;
    o.x = xv.x * dinv; o.y = xv.y * dinv; o.z = xv.z * dinv; o.w = xv.w * dinv;
    reinterpret_cast<float4*>(g_acc)[idx] = o;
}

// ---------------------------------------------------------------------------
// K3: scatter — for each edge (s -> d): acc[d][:] += x[s][:] * dinv[s]
// One warp per edge; 32 edges batched per warp via coalesced index loads +
// shuffle. Each lane: 1x LDG.128 gather + 1x red.global.add.v4.f32.
// ---------------------------------------------------------------------------
__global__ void k_scatter(const float* __restrict__ x,
                          const int* __restrict__ rowi,
                          const int* __restrict__ coli, int E) {
    int gwarp = (blockIdx.x * blockDim.x + threadIdx.x) >> 5;
    int lane  = threadIdx.x & 31;
    int base  = gwarp * 32;
    if (base >= E) return;

    int me = base + lane;
    int s = 0, d = 0;
    float di = 0.0f;
    if (me < E) {
        s = rowi[me];
        d = coli[me];
        di = g_dinv[s];
    }
    int cnt = min(32, E - base);
    const float4* x4 = reinterpret_cast<const float4*>(x);

    #pragma unroll 1
    for (int e = 0; e < cnt; ++e) {
        int   se = __shfl_sync(0xffffffffu, s, e);
        int   de = __shfl_sync(0xffffffffu, d, e);
        float dv = __shfl_sync(0xffffffffu, di, e);
        float4 v = __ldg(x4 + (size_t)se * F4 + lane);
        float* dst = g_acc + (size_t)de * F_IN + lane * 4;
        asm volatile("red.global.add.v4.f32 [%0], {%1, %2, %3, %4};"
                     :: "l"(dst),
                        "f"(v.x * dv), "f"(v.y * dv), "f"(v.z * dv), "f"(v.w * dv)
                     : "memory");
    }
}

// ---------------------------------------------------------------------------
// K4: fused GEMM + bias:  out = (acc * dinv) @ [W_mu | W_logstd] + [b_mu | b_ls]
// Block: 256 threads, one 64-row tile per block, all 128 combined output cols.
// Thread tile: 8 rows x 4 cols. W (128x128) + A tile (64x128) + bias in
// dynamic shared (96.5 KB).
// ---------------------------------------------------------------------------
__global__ void k_gemm(const float* __restrict__ Wmu, const float* __restrict__ bmu,
                       const float* __restrict__ Wls, const float* __restrict__ bls,
                       float* __restrict__ out, int n) {
    extern __shared__ float smem[];
    float* Ws = smem;             // 128*128 = 16384 floats, layout [k][j]
    float* As = smem + 16384;     // 64*128  =  8192 floats, layout [r][k]
    float* bs = smem + 16384 + 8192;  // 128 floats

    int tid = threadIdx.x;

    // load combined W into shared: Ws[k*128 + j]
    for (int i = tid; i < 128 * 128; i += 256) {
        int k = i >> 7, j = i & 127;
        Ws[i] = (j < 64) ? Wmu[k * 64 + j] : Wls[k * 64 + (j - 64)];
    }
    if (tid < 128) bs[tid] = (tid < 64) ? bmu[tid] : bls[tid - 64];

    // load A tile (64 rows) with dinv scaling
    int rowbase = blockIdx.x * 64;
    float4* As4 = reinterpret_cast<float4*>(As);
    for (int t = tid; t < 64 * F4; t += 256) {
        int r = t >> 5, c = t & 31;
        int v = rowbase + r;
        float4 a = make_float4(0.f, 0.f, 0.f, 0.f);
        if (v < n) {
            float dv = g_dinv[v];
            float4 g = reinterpret_cast<const float4*>(g_acc)[(size_t)v * F4 + c];
            a.x = g.x * dv; a.y = g.y * dv; a.z = g.z * dv; a.w = g.w * dv;
        }
        As4[t] = a;
    }
    __syncthreads();

    int tx = tid & 31;   // col group: cols [4*tx, 4*tx+4)
    int ty = tid >> 5;   // row group: rows [8*ty, 8*ty+8)

    float4 acc[8];
    {
        float4 b4 = reinterpret_cast<float4*>(bs)[tx];
        #pragma unroll
        for (int r = 0; r < 8; ++r) acc[r] = b4;
    }

    const float4* Ws4 = reinterpret_cast<const float4*>(Ws);
    #pragma unroll 4
    for (int k4 = 0; k4 < 32; ++k4) {
        float4 w0 = Ws4[(k4 * 4 + 0) * 32 + tx];
        float4 w1 = Ws4[(k4 * 4 + 1) * 32 + tx];
        float4 w2 = Ws4[(k4 * 4 + 2) * 32 + tx];
        float4 w3 = Ws4[(k4 * 4 + 3) * 32 + tx];
        #pragma unroll
        for (int r = 0; r < 8; ++r) {
            float4 a = As4[(ty * 8 + r) * 32 + k4];   // warp-broadcast
            acc[r].x += a.x * w0.x + a.y * w1.x + a.z * w2.x + a.w * w3.x;
            acc[r].y += a.x * w0.y + a.y * w1.y + a.z * w2.y + a.w * w3.y;
            acc[r].z += a.x * w0.z + a.y * w1.z + a.z * w2.z + a.w * w3.z;
            acc[r].w += a.x * w0.w + a.y * w1.w + a.z * w2.w + a.w * w3.w;
        }
    }

    // store: cols [0,64) -> mu, cols [64,128) -> logstd
    float* outm = out;
    float* outl = out + (size_t)n * 64;
    #pragma unroll
    for (int r = 0; r < 8; ++r) {
        int v = rowbase + ty * 8 + r;
        if (v < n) {
            if (tx < 16) {
                reinterpret_cast<float4*>(outm + (size_t)v * 64)[tx] = acc[r];
            } else {
                reinterpret_cast<float4*>(outl + (size_t)v * 64)[tx - 16] = acc[r];
            }
        }
    }
}

// ---------------------------------------------------------------------------
// launch
// ---------------------------------------------------------------------------
extern "C" void kernel_launch(void* const* d_in, const int* in_sizes, int n_in,
                              void* d_out, int out_size) {
    const float* x   = (const float*)d_in[0];
    const int*   ei  = (const int*)d_in[1];
    const float* Wmu = (const float*)d_in[2];
    const float* bmu = (const float*)d_in[3];
    const float* Wls = (const float*)d_in[4];
    const float* bls = (const float*)d_in[5];

    int n = in_sizes[0] / F_IN;     // 100000
    int E = in_sizes[1] / 2;        // 3200000
    const int* rowi = ei;           // edge_index[0]
    const int* coli = ei + E;       // edge_index[1]

    k_init_deg<<<(n + 255) / 256, 256>>>(n);
    k_count<<<((E + 3) / 4 + 255) / 256, 256>>>(coli, E);
    k_selfinit<<<(n * F4 + 255) / 256, 256>>>(x, n);
    // one warp per 32 edges, 8 warps/block -> 256 edges per block
    k_scatter<<<(E + 255) / 256, 256>>>(x, rowi, coli, E);

    int smem_bytes = (16384 + 8192 + 128) * (int)sizeof(float);  // 98816 B
    cudaFuncSetAttribute(k_gemm, cudaFuncAttributeMaxDynamicSharedMemorySize,
                         smem_bytes);
    k_gemm<<<(n + 63) / 64, 256, smem_bytes>>>(Wmu, bmu, Wls, bls,
                                               (float*)d_out, n);
}

// round 6
// speedup vs baseline: 1.4410x; 1.4410x over previous
#include <cuda_runtime.h>
#include <stdint.h>

#define NNODES_MAX 100000
#define NEDGES_MAX 3200000
#define F_IN 128
#define F4 32            // float4s per feature row
#define SCAN_BLK 1024

// ---- scratch (static __device__ globals; allocation-free) ----
__device__ int   g_deg[NNODES_MAX];        // in-degree -> placement cursor -> count
__device__ int   g_off[NNODES_MAX];        // CSR offsets (exclusive scan of indeg)
__device__ int   g_bsum[128];              // block sums for scan
__device__ float g_dinv[NNODES_MAX];
__device__ int2  g_edge[NEDGES_MAX];       // per-edge (src, dinv[src] bits), dst-sorted
__device__ float g_acc[(size_t)NNODES_MAX * F_IN];

// ---------------------------------------------------------------------------
// K0: zero degree counters (device globals persist across graph replays)
// ---------------------------------------------------------------------------
__global__ void k_zero(int n) {
    int v = blockIdx.x * blockDim.x + threadIdx.x;
    if (v < n) g_deg[v] = 0;
}

// ---------------------------------------------------------------------------
// K1: in-degree count: deg[col[e]] += 1
// ---------------------------------------------------------------------------
__global__ void k_count(const int* __restrict__ col, int E) {
    int i = blockIdx.x * blockDim.x + threadIdx.x;
    int base = i * 4;
    if (base + 3 < E) {
        int4 c = *reinterpret_cast<const int4*>(col + base);
        atomicAdd(&g_deg[c.x], 1);
        atomicAdd(&g_deg[c.y], 1);
        atomicAdd(&g_deg[c.z], 1);
        atomicAdd(&g_deg[c.w], 1);
    } else if (base < E) {
        for (int e = base; e < E; ++e) atomicAdd(&g_deg[col[e]], 1);
    }
}

// ---------------------------------------------------------------------------
// K2a: per-block exclusive scan of indeg -> g_off, block totals -> g_bsum
// ---------------------------------------------------------------------------
__global__ void k_scan_part(int n) {
    __shared__ int s[SCAN_BLK];
    int tid = threadIdx.x;
    int v = blockIdx.x * SCAN_BLK + tid;
    int val = (v < n) ? g_deg[v] : 0;
    s[tid] = val;
    __syncthreads();
    #pragma unroll
    for (int off = 1; off < SCAN_BLK; off <<= 1) {
        int t = (tid >= off) ? s[tid - off] : 0;
        __syncthreads();
        s[tid] += t;
        __syncthreads();
    }
    if (v < n) g_off[v] = s[tid] - val;           // exclusive within block
    if (tid == SCAN_BLK - 1) g_bsum[blockIdx.x] = s[tid];
}

// K2b: scan the (<=128) block sums in one block
__global__ void k_scan_sums(int nb) {
    __shared__ int s[128];
    int tid = threadIdx.x;
    int val = (tid < nb) ? g_bsum[tid] : 0;
    s[tid] = val;
    __syncthreads();
    #pragma unroll
    for (int off = 1; off < 128; off <<= 1) {
        int t = (tid >= off) ? s[tid - off] : 0;
        __syncthreads();
        s[tid] += t;
        __syncthreads();
    }
    if (tid < nb) g_bsum[tid] = s[tid] - val;     // exclusive
}

// K2c: add block bases; compute dinv = rsqrt(indeg+1); reset deg -> cursor 0
__global__ void k_scan_add(int n) {
    int v = blockIdx.x * blockDim.x + threadIdx.x;
    if (v >= n) return;
    g_off[v] += g_bsum[v / SCAN_BLK];
    g_dinv[v] = rsqrtf((float)(g_deg[v] + 1));
    g_deg[v] = 0;                                  // reuse as placement cursor
}

// ---------------------------------------------------------------------------
// K3: permute edges into dst-sorted order, packing (src, dinv[src])
// ---------------------------------------------------------------------------
__global__ void k_permute(const int* __restrict__ rowi,
                          const int* __restrict__ coli, int E) {
    int i = blockIdx.x * blockDim.x + threadIdx.x;
    int base = i * 4;
    if (base + 3 < E) {
        int4 s4 = *reinterpret_cast<const int4*>(rowi + base);
        int4 d4 = *reinterpret_cast<const int4*>(coli + base);
        int p;
        p = g_off[d4.x] + atomicAdd(&g_deg[d4.x], 1);
        g_edge[p] = make_int2(s4.x, __float_as_int(g_dinv[s4.x]));
        p = g_off[d4.y] + atomicAdd(&g_deg[d4.y], 1);
        g_edge[p] = make_int2(s4.y, __float_as_int(g_dinv[s4.y]));
        p = g_off[d4.z] + atomicAdd(&g_deg[d4.z], 1);
        g_edge[p] = make_int2(s4.z, __float_as_int(g_dinv[s4.z]));
        p = g_off[d4.w] + atomicAdd(&g_deg[d4.w], 1);
        g_edge[p] = make_int2(s4.w, __float_as_int(g_dinv[s4.w]));
    } else if (base < E) {
        for (int e = base; e < E; ++e) {
            int s = rowi[e], d = coli[e];
            int p = g_off[d] + atomicAdd(&g_deg[d], 1);
            g_edge[p] = make_int2(s, __float_as_int(g_dinv[s]));
        }
    }
}

// ---------------------------------------------------------------------------
// K4: gather-aggregate. One warp per dst node. Registers accumulate, one
// plain STG.128 per lane at the end. Fuses self-loop and dinv[dst] scale.
//   acc[v] = dinv[v] * ( x[v]*dinv[v] + sum_e dinv[src_e]*x[src_e] )
// ---------------------------------------------------------------------------
__global__ void k_gather(const float* __restrict__ x, int n) {
    int gwarp = (blockIdx.x * blockDim.x + threadIdx.x) >> 5;
    int lane  = threadIdx.x & 31;
    if (gwarp >= n) return;
    int v = gwarp;

    const float4* x4 = reinterpret_cast<const float4*>(x);
    float dv_dst = g_dinv[v];
    int offs = g_off[v];
    int cnt  = g_deg[v];          // == indeg after permute

    // self-loop term
    float4 xv = __ldg(x4 + (size_t)v * F4 + lane);
    float4 acc;
    acc.x = xv.x * dv_dst; acc.y = xv.y * dv_dst;
    acc.z = xv.z * dv_dst; acc.w = xv.w * dv_dst;

    for (int base = 0; base < cnt; base += 32) {
        int m = min(32, cnt - base);
        int2 ed = make_int2(0, 0);
        if (base + lane < cnt)
            ed = __ldg(&g_edge[offs + base + lane]);

        int e = 0;
        for (; e + 1 < m; e += 2) {
            int   s0 = __shfl_sync(0xffffffffu, ed.x, e);
            float c0 = __int_as_float(__shfl_sync(0xffffffffu, ed.y, e));
            int   s1 = __shfl_sync(0xffffffffu, ed.x, e + 1);
            float c1 = __int_as_float(__shfl_sync(0xffffffffu, ed.y, e + 1));
            float4 v0 = __ldg(x4 + (size_t)s0 * F4 + lane);
            float4 v1 = __ldg(x4 + (size_t)s1 * F4 + lane);
            acc.x += v0.x * c0; acc.y += v0.y * c0;
            acc.z += v0.z * c0; acc.w += v0.w * c0;
            acc.x += v1.x * c1; acc.y += v1.y * c1;
            acc.z += v1.z * c1; acc.w += v1.w * c1;
        }
        if (e < m) {
            int   s0 = __shfl_sync(0xffffffffu, ed.x, e);
            float c0 = __int_as_float(__shfl_sync(0xffffffffu, ed.y, e));
            float4 v0 = __ldg(x4 + (size_t)s0 * F4 + lane);
            acc.x += v0.x * c0; acc.y += v0.y * c0;
            acc.z += v0.z * c0; acc.w += v0.w * c0;
        }
    }

    acc.x *= dv_dst; acc.y *= dv_dst; acc.z *= dv_dst; acc.w *= dv_dst;
    reinterpret_cast<float4*>(g_acc)[(size_t)v * F4 + lane] = acc;
}

// ---------------------------------------------------------------------------
// K5: fused GEMM + bias:  out = g_acc @ [W_mu | W_logstd] + [b_mu | b_ls]
// ---------------------------------------------------------------------------
__global__ void k_gemm(const float* __restrict__ Wmu, const float* __restrict__ bmu,
                       const float* __restrict__ Wls, const float* __restrict__ bls,
                       float* __restrict__ out, int n) {
    extern __shared__ float smem[];
    float* Ws = smem;                 // 128*128 floats, layout [k][j]
    float* As = smem + 16384;         // 64*128 floats, layout [r][k]
    float* bs = smem + 16384 + 8192;  // 128 floats

    int tid = threadIdx.x;

    for (int i = tid; i < 128 * 128; i += 256) {
        int k = i >> 7, j = i & 127;
        Ws[i] = (j < 64) ? Wmu[k * 64 + j] : Wls[k * 64 + (j - 64)];
    }
    if (tid < 128) bs[tid] = (tid < 64) ? bmu[tid] : bls[tid - 64];

    int rowbase = blockIdx.x * 64;
    float4* As4 = reinterpret_cast<float4*>(As);
    for (int t = tid; t < 64 * F4; t += 256) {
        int r = t >> 5, c = t & 31;
        int v = rowbase + r;
        float4 a = make_float4(0.f, 0.f, 0.f, 0.f);
        if (v < n) a = reinterpret_cast<const float4*>(g_acc)[(size_t)v * F4 + c];
        As4[t] = a;
    }
    __syncthreads();

    int tx = tid & 31;   // cols [4*tx, 4*tx+4)
    int ty = tid >> 5;   // rows [8*ty, 8*ty+8)

    float4 acc[8];
    {
        float4 b4 = reinterpret_cast<float4*>(bs)[tx];
        #pragma unroll
        for (int r = 0; r < 8; ++r) acc[r] = b4;
    }

    const float4* Ws4 = reinterpret_cast<const float4*>(Ws);
    #pragma unroll 4
    for (int k4 = 0; k4 < 32; ++k4) {
        float4 w0 = Ws4[(k4 * 4 + 0) * 32 + tx];
        float4 w1 = Ws4[(k4 * 4 + 1) * 32 + tx];
        float4 w2 = Ws4[(k4 * 4 + 2) * 32 + tx];
        float4 w3 = Ws4[(k4 * 4 + 3) * 32 + tx];
        #pragma unroll
        for (int r = 0; r < 8; ++r) {
            float4 a = As4[(ty * 8 + r) * 32 + k4];
            acc[r].x += a.x * w0.x + a.y * w1.x + a.z * w2.x + a.w * w3.x;
            acc[r].y += a.x * w0.y + a.y * w1.y + a.z * w2.y + a.w * w3.y;
            acc[r].z += a.x * w0.z + a.y * w1.z + a.z * w2.z + a.w * w3.z;
            acc[r].w += a.x * w0.w + a.y * w1.w + a.z * w2.w + a.w * w3.w;
        }
    }

    float* outm = out;
    float* outl = out + (size_t)n * 64;
    #pragma unroll
    for (int r = 0; r < 8; ++r) {
        int v = rowbase + ty * 8 + r;
        if (v < n) {
            if (tx < 16) {
                reinterpret_cast<float4*>(outm + (size_t)v * 64)[tx] = acc[r];
            } else {
                reinterpret_cast<float4*>(outl + (size_t)v * 64)[tx - 16] = acc[r];
            }
        }
    }
}

// ---------------------------------------------------------------------------
// launch
// ---------------------------------------------------------------------------
extern "C" void kernel_launch(void* const* d_in, const int* in_sizes, int n_in,
                              void* d_out, int out_size) {
    const float* x   = (const float*)d_in[0];
    const int*   ei  = (const int*)d_in[1];
    const float* Wmu = (const float*)d_in[2];
    const float* bmu = (const float*)d_in[3];
    const float* Wls = (const float*)d_in[4];
    const float* bls = (const float*)d_in[5];

    int n = in_sizes[0] / F_IN;     // 100000
    int E = in_sizes[1] / 2;        // 3200000
    const int* rowi = ei;           // edge_index[0] (src)
    const int* coli = ei + E;       // edge_index[1] (dst)

    int nb = (n + SCAN_BLK - 1) / SCAN_BLK;   // 98

    k_zero<<<(n + 255) / 256, 256>>>(n);
    k_count<<<((E + 3) / 4 + 255) / 256, 256>>>(coli, E);
    k_scan_part<<<nb, SCAN_BLK>>>(n);
    k_scan_sums<<<1, 128>>>(nb);
    k_scan_add<<<(n + 255) / 256, 256>>>(n);
    k_permute<<<((E + 3) / 4 + 255) / 256, 256>>>(rowi, coli, E);
    k_gather<<<(n * 32 + 255) / 256, 256>>>(x, n);

    int smem_bytes = (16384 + 8192 + 128) * (int)sizeof(float);  // 98816 B
    cudaFuncSetAttribute(k_gemm, cudaFuncAttributeMaxDynamicSharedMemorySize,
                         smem_bytes);
    k_gemm<<<(n + 63) / 64, 256, smem_bytes>>>(Wmu, bmu, Wls, bls,
                                               (float*)d_out, n);
}

// round 7
// speedup vs baseline: 1.5517x; 1.0768x over previous
#include <cuda_runtime.h>
#include <cuda_fp16.h>
#include <stdint.h>

#define NNODES_MAX 100000
#define NEDGES_MAX 3200000
#define F_IN 128
#define F4 32            // float4s per feature row
#define H2_ROW 32        // uint2 (4 halves) per feature row
#define SCAN_BLK 1024

// ---- scratch (static __device__ globals; allocation-free) ----
__device__ int   g_deg[NNODES_MAX];        // in-degree -> placement cursor -> count
__device__ int   g_off[NNODES_MAX];        // CSR offsets (exclusive scan of indeg)
__device__ int   g_bsum[128];              // block sums for scan
__device__ float g_dinv[NNODES_MAX];
__device__ int   g_edge[NEDGES_MAX];       // src per edge, dst-sorted (dinv folded into xh)
__device__ uint2 g_xh[(size_t)NNODES_MAX * H2_ROW];   // fp16(x * dinv[row]), 25.6MB
__device__ float g_acc[(size_t)NNODES_MAX * F_IN];

// ---------------------------------------------------------------------------
// K0: zero degree counters
// ---------------------------------------------------------------------------
__global__ void k_zero(int n) {
    int v = blockIdx.x * blockDim.x + threadIdx.x;
    if (v < n) g_deg[v] = 0;
}

// ---------------------------------------------------------------------------
// K1: in-degree count: deg[col[e]] += 1
// ---------------------------------------------------------------------------
__global__ void k_count(const int* __restrict__ col, int E) {
    int i = blockIdx.x * blockDim.x + threadIdx.x;
    int base = i * 4;
    if (base + 3 < E) {
        int4 c = *reinterpret_cast<const int4*>(col + base);
        atomicAdd(&g_deg[c.x], 1);
        atomicAdd(&g_deg[c.y], 1);
        atomicAdd(&g_deg[c.z], 1);
        atomicAdd(&g_deg[c.w], 1);
    } else if (base < E) {
        for (int e = base; e < E; ++e) atomicAdd(&g_deg[col[e]], 1);
    }
}

// ---------------------------------------------------------------------------
// K2a: per-block exclusive scan of indeg -> g_off, block totals -> g_bsum
// ---------------------------------------------------------------------------
__global__ void k_scan_part(int n) {
    __shared__ int s[SCAN_BLK];
    int tid = threadIdx.x;
    int v = blockIdx.x * SCAN_BLK + tid;
    int val = (v < n) ? g_deg[v] : 0;
    s[tid] = val;
    __syncthreads();
    #pragma unroll
    for (int off = 1; off < SCAN_BLK; off <<= 1) {
        int t = (tid >= off) ? s[tid - off] : 0;
        __syncthreads();
        s[tid] += t;
        __syncthreads();
    }
    if (v < n) g_off[v] = s[tid] - val;
    if (tid == SCAN_BLK - 1) g_bsum[blockIdx.x] = s[tid];
}

// K2b: scan block sums
__global__ void k_scan_sums(int nb) {
    __shared__ int s[128];
    int tid = threadIdx.x;
    int val = (tid < nb) ? g_bsum[tid] : 0;
    s[tid] = val;
    __syncthreads();
    #pragma unroll
    for (int off = 1; off < 128; off <<= 1) {
        int t = (tid >= off) ? s[tid - off] : 0;
        __syncthreads();
        s[tid] += t;
        __syncthreads();
    }
    if (tid < nb) g_bsum[tid] = s[tid] - val;
}

// K2c: add block bases; dinv = rsqrt(indeg+1); reset deg -> cursor
__global__ void k_scan_add(int n) {
    int v = blockIdx.x * blockDim.x + threadIdx.x;
    if (v >= n) return;
    g_off[v] += g_bsum[v / SCAN_BLK];
    g_dinv[v] = rsqrtf((float)(g_deg[v] + 1));
    g_deg[v] = 0;
}

// ---------------------------------------------------------------------------
// K3: prescale x by dinv[row] into fp16 (folds dinv[src] into the data)
// one thread per 4 features
// ---------------------------------------------------------------------------
__global__ void k_prescale(const float* __restrict__ x, int n) {
    int idx = blockIdx.x * blockDim.x + threadIdx.x;
    if (idx >= n * F4) return;
    int v = idx >> 5;
    float dv = g_dinv[v];
    float4 xv = reinterpret_cast<const float4*>(x)[idx];
    __half2 h0 = __floats2half2_rn(xv.x * dv, xv.y * dv);
    __half2 h1 = __floats2half2_rn(xv.z * dv, xv.w * dv);
    uint2 o;
    o.x = *reinterpret_cast<unsigned*>(&h0);
    o.y = *reinterpret_cast<unsigned*>(&h1);
    g_xh[idx] = o;
}

// ---------------------------------------------------------------------------
// K4: permute edges into dst-sorted order (src index only, 4B records)
// ---------------------------------------------------------------------------
__global__ void k_permute(const int* __restrict__ rowi,
                          const int* __restrict__ coli, int E) {
    int i = blockIdx.x * blockDim.x + threadIdx.x;
    int base = i * 4;
    if (base + 3 < E) {
        int4 s4 = *reinterpret_cast<const int4*>(rowi + base);
        int4 d4 = *reinterpret_cast<const int4*>(coli + base);
        g_edge[g_off[d4.x] + atomicAdd(&g_deg[d4.x], 1)] = s4.x;
        g_edge[g_off[d4.y] + atomicAdd(&g_deg[d4.y], 1)] = s4.y;
        g_edge[g_off[d4.z] + atomicAdd(&g_deg[d4.z], 1)] = s4.z;
        g_edge[g_off[d4.w] + atomicAdd(&g_deg[d4.w], 1)] = s4.w;
    } else if (base < E) {
        for (int e = base; e < E; ++e) {
            int s = rowi[e], d = coli[e];
            g_edge[g_off[d] + atomicAdd(&g_deg[d], 1)] = s;
        }
    }
}

// ---------------------------------------------------------------------------
// K5: gather-aggregate (fp16 rows, fp32 accumulate). One warp per dst node.
//   acc[v] = dinv[v] * ( xh[v] + sum_e xh[src_e] )      (xh = x * dinv)
// each lane owns 4 features (8 bytes of the fp16 row).
// ---------------------------------------------------------------------------
__global__ void k_gather(int n) {
    int gwarp = (blockIdx.x * blockDim.x + threadIdx.x) >> 5;
    int lane  = threadIdx.x & 31;
    if (gwarp >= n) return;
    int v = gwarp;

    float dv_dst = g_dinv[v];
    int offs = g_off[v];
    int cnt  = g_deg[v];

    // self-loop term
    float ax, ay, az, aw;
    {
        uint2 h = __ldg(&g_xh[(size_t)v * H2_ROW + lane]);
        float2 f0 = __half22float2(*reinterpret_cast<__half2*>(&h.x));
        float2 f1 = __half22float2(*reinterpret_cast<__half2*>(&h.y));
        ax = f0.x; ay = f0.y; az = f1.x; aw = f1.y;
    }

    for (int base = 0; base < cnt; base += 32) {
        int m = min(32, cnt - base);
        int s = 0;
        if (base + lane < cnt) s = __ldg(&g_edge[offs + base + lane]);

        int e = 0;
        for (; e + 3 < m; e += 4) {
            int s0 = __shfl_sync(0xffffffffu, s, e);
            int s1 = __shfl_sync(0xffffffffu, s, e + 1);
            int s2 = __shfl_sync(0xffffffffu, s, e + 2);
            int s3 = __shfl_sync(0xffffffffu, s, e + 3);
            uint2 h0 = __ldg(&g_xh[(size_t)s0 * H2_ROW + lane]);
            uint2 h1 = __ldg(&g_xh[(size_t)s1 * H2_ROW + lane]);
            uint2 h2 = __ldg(&g_xh[(size_t)s2 * H2_ROW + lane]);
            uint2 h3 = __ldg(&g_xh[(size_t)s3 * H2_ROW + lane]);
            float2 a, b;
            a = __half22float2(*reinterpret_cast<__half2*>(&h0.x));
            b = __half22float2(*reinterpret_cast<__half2*>(&h0.y));
            ax += a.x; ay += a.y; az += b.x; aw += b.y;
            a = __half22float2(*reinterpret_cast<__half2*>(&h1.x));
            b = __half22float2(*reinterpret_cast<__half2*>(&h1.y));
            ax += a.x; ay += a.y; az += b.x; aw += b.y;
            a = __half22float2(*reinterpret_cast<__half2*>(&h2.x));
            b = __half22float2(*reinterpret_cast<__half2*>(&h2.y));
            ax += a.x; ay += a.y; az += b.x; aw += b.y;
            a = __half22float2(*reinterpret_cast<__half2*>(&h3.x));
            b = __half22float2(*reinterpret_cast<__half2*>(&h3.y));
            ax += a.x; ay += a.y; az += b.x; aw += b.y;
        }
        for (; e < m; ++e) {
            int s0 = __shfl_sync(0xffffffffu, s, e);
            uint2 h0 = __ldg(&g_xh[(size_t)s0 * H2_ROW + lane]);
            float2 a = __half22float2(*reinterpret_cast<__half2*>(&h0.x));
            float2 b = __half22float2(*reinterpret_cast<__half2*>(&h0.y));
            ax += a.x; ay += a.y; az += b.x; aw += b.y;
        }
    }

    float4 o;
    o.x = ax * dv_dst; o.y = ay * dv_dst; o.z = az * dv_dst; o.w = aw * dv_dst;
    reinterpret_cast<float4*>(g_acc)[(size_t)v * F4 + lane] = o;
}

// ---------------------------------------------------------------------------
// K6: fused GEMM + bias:  out = g_acc @ [W_mu | W_logstd] + [b_mu | b_ls]
// ---------------------------------------------------------------------------
__global__ void k_gemm(const float* __restrict__ Wmu, const float* __restrict__ bmu,
                       const float* __restrict__ Wls, const float* __restrict__ bls,
                       float* __restrict__ out, int n) {
    extern __shared__ float smem[];
    float* Ws = smem;                 // 128*128 floats, layout [k][j]
    float* As = smem + 16384;         // 64*128 floats, layout [r][k]
    float* bs = smem + 16384 + 8192;  // 128 floats

    int tid = threadIdx.x;

    for (int i = tid; i < 128 * 128; i += 256) {
        int k = i >> 7, j = i & 127;
        Ws[i] = (j < 64) ? Wmu[k * 64 + j] : Wls[k * 64 + (j - 64)];
    }
    if (tid < 128) bs[tid] = (tid < 64) ? bmu[tid] : bls[tid - 64];

    int rowbase = blockIdx.x * 64;
    float4* As4 = reinterpret_cast<float4*>(As);
    for (int t = tid; t < 64 * F4; t += 256) {
        int r = t >> 5, c = t & 31;
        int v = rowbase + r;
        float4 a = make_float4(0.f, 0.f, 0.f, 0.f);
        if (v < n) a = reinterpret_cast<const float4*>(g_acc)[(size_t)v * F4 + c];
        As4[t] = a;
    }
    __syncthreads();

    int tx = tid & 31;   // cols [4*tx, 4*tx+4)
    int ty = tid >> 5;   // rows [8*ty, 8*ty+8)

    float4 acc[8];
    {
        float4 b4 = reinterpret_cast<float4*>(bs)[tx];
        #pragma unroll
        for (int r = 0; r < 8; ++r) acc[r] = b4;
    }

    const float4* Ws4 = reinterpret_cast<const float4*>(Ws);
    #pragma unroll 4
    for (int k4 = 0; k4 < 32; ++k4) {
        float4 w0 = Ws4[(k4 * 4 + 0) * 32 + tx];
        float4 w1 = Ws4[(k4 * 4 + 1) * 32 + tx];
        float4 w2 = Ws4[(k4 * 4 + 2) * 32 + tx];
        float4 w3 = Ws4[(k4 * 4 + 3) * 32 + tx];
        #pragma unroll
        for (int r = 0; r < 8; ++r) {
            float4 a = As4[(ty * 8 + r) * 32 + k4];
            acc[r].x += a.x * w0.x + a.y * w1.x + a.z * w2.x + a.w * w3.x;
            acc[r].y += a.x * w0.y + a.y * w1.y + a.z * w2.y + a.w * w3.y;
            acc[r].z += a.x * w0.z + a.y * w1.z + a.z * w2.z + a.w * w3.z;
            acc[r].w += a.x * w0.w + a.y * w1.w + a.z * w2.w + a.w * w3.w;
        }
    }

    float* outm = out;
    float* outl = out + (size_t)n * 64;
    #pragma unroll
    for (int r = 0; r < 8; ++r) {
        int v = rowbase + ty * 8 + r;
        if (v < n) {
            if (tx < 16) {
                reinterpret_cast<float4*>(outm + (size_t)v * 64)[tx] = acc[r];
            } else {
                reinterpret_cast<float4*>(outl + (size_t)v * 64)[tx - 16] = acc[r];
            }
        }
    }
}

// ---------------------------------------------------------------------------
// launch
// ---------------------------------------------------------------------------
extern "C" void kernel_launch(void* const* d_in, const int* in_sizes, int n_in,
                              void* d_out, int out_size) {
    const float* x   = (const float*)d_in[0];
    const int*   ei  = (const int*)d_in[1];
    const float* Wmu = (const float*)d_in[2];
    const float* bmu = (const float*)d_in[3];
    const float* Wls = (const float*)d_in[4];
    const float* bls = (const float*)d_in[5];

    int n = in_sizes[0] / F_IN;     // 100000
    int E = in_sizes[1] / 2;        // 3200000
    const int* rowi = ei;           // edge_index[0] (src)
    const int* coli = ei + E;       // edge_index[1] (dst)

    int nb = (n + SCAN_BLK - 1) / SCAN_BLK;   // 98

    k_zero<<<(n + 255) / 256, 256>>>(n);
    k_count<<<((E + 3) / 4 + 255) / 256, 256>>>(coli, E);
    k_scan_part<<<nb, SCAN_BLK>>>(n);
    k_scan_sums<<<1, 128>>>(nb);
    k_scan_add<<<(n + 255) / 256, 256>>>(n);
    k_prescale<<<(n * F4 + 255) / 256, 256>>>(x, n);
    k_permute<<<((E + 3) / 4 + 255) / 256, 256>>>(rowi, coli, E);
    k_gather<<<(n * 32 + 255) / 256, 256>>>(n);

    int smem_bytes = (16384 + 8192 + 128) * (int)sizeof(float);  // 98816 B
    cudaFuncSetAttribute(k_gemm, cudaFuncAttributeMaxDynamicSharedMemorySize,
                         smem_bytes);
    k_gemm<<<(n + 63) / 64, 256, smem_bytes>>>(Wmu, bmu, Wls, bls,
                                               (float*)d_out, n);
}

// round 8
// speedup vs baseline: 2.3698x; 1.5272x over previous
#include <cuda_runtime.h>
#include <cuda_fp16.h>
#include <stdint.h>

#define NNODES_MAX 100000
#define NROWS_PAD  100096     // 782 * 128, padded for 128-row GEMM tiles
#define NEDGES_MAX 3200000
#define F_IN 128
#define F4 32            // float4s per feature row
#define H2_ROW 32        // uint2 (4 halves) per feature row
#define SCAN_BLK 1024

// ---- scratch (static __device__ globals; allocation-free, zero-initialized) ----
__device__ int    g_deg[NNODES_MAX];
__device__ int    g_off[NNODES_MAX];
__device__ int    g_bsum[128];
__device__ float  g_dinv[NNODES_MAX];
__device__ int    g_edge[NEDGES_MAX];                    // src per edge, dst-sorted
__device__ uint2  g_xh[(size_t)NNODES_MAX * H2_ROW];     // fp16(x * dinv[row])
__device__ uint2  g_acch[(size_t)NROWS_PAD * H2_ROW];    // fp16 aggregated features
__device__ __half g_wh[128 * 128];                       // combined [W_mu|W_ls] fp16, [k][j]
__device__ float  g_bias[128];                           // combined bias

// ---------------------------------------------------------------------------
// K0: zero degree counters
// ---------------------------------------------------------------------------
__global__ void k_zero(int n) {
    int v = blockIdx.x * blockDim.x + threadIdx.x;
    if (v < n) g_deg[v] = 0;
}

// ---------------------------------------------------------------------------
// K1: in-degree count
// ---------------------------------------------------------------------------
__global__ void k_count(const int* __restrict__ col, int E) {
    int i = blockIdx.x * blockDim.x + threadIdx.x;
    int base = i * 4;
    if (base + 3 < E) {
        int4 c = *reinterpret_cast<const int4*>(col + base);
        atomicAdd(&g_deg[c.x], 1);
        atomicAdd(&g_deg[c.y], 1);
        atomicAdd(&g_deg[c.z], 1);
        atomicAdd(&g_deg[c.w], 1);
    } else if (base < E) {
        for (int e = base; e < E; ++e) atomicAdd(&g_deg[col[e]], 1);
    }
}

// ---------------------------------------------------------------------------
// K2a/b/c: exclusive scan of indeg -> g_off ; dinv ; reset cursors
// ---------------------------------------------------------------------------
__global__ void k_scan_part(int n) {
    __shared__ int s[SCAN_BLK];
    int tid = threadIdx.x;
    int v = blockIdx.x * SCAN_BLK + tid;
    int val = (v < n) ? g_deg[v] : 0;
    s[tid] = val;
    __syncthreads();
    #pragma unroll
    for (int off = 1; off < SCAN_BLK; off <<= 1) {
        int t = (tid >= off) ? s[tid - off] : 0;
        __syncthreads();
        s[tid] += t;
        __syncthreads();
    }
    if (v < n) g_off[v] = s[tid] - val;
    if (tid == SCAN_BLK - 1) g_bsum[blockIdx.x] = s[tid];
}

__global__ void k_scan_sums(int nb) {
    __shared__ int s[128];
    int tid = threadIdx.x;
    int val = (tid < nb) ? g_bsum[tid] : 0;
    s[tid] = val;
    __syncthreads();
    #pragma unroll
    for (int off = 1; off < 128; off <<= 1) {
        int t = (tid >= off) ? s[tid - off] : 0;
        __syncthreads();
        s[tid] += t;
        __syncthreads();
    }
    if (tid < nb) g_bsum[tid] = s[tid] - val;
}

__global__ void k_scan_add(int n) {
    int v = blockIdx.x * blockDim.x + threadIdx.x;
    if (v >= n) return;
    g_off[v] += g_bsum[v / SCAN_BLK];
    g_dinv[v] = rsqrtf((float)(g_deg[v] + 1));
    g_deg[v] = 0;
}

// ---------------------------------------------------------------------------
// K3: prescale x by dinv[row] into fp16
// ---------------------------------------------------------------------------
__global__ void k_prescale(const float* __restrict__ x, int n) {
    int idx = blockIdx.x * blockDim.x + threadIdx.x;
    if (idx >= n * F4) return;
    int v = idx >> 5;
    float dv = g_dinv[v];
    float4 xv = reinterpret_cast<const float4*>(x)[idx];
    __half2 h0 = __floats2half2_rn(xv.x * dv, xv.y * dv);
    __half2 h1 = __floats2half2_rn(xv.z * dv, xv.w * dv);
    uint2 o;
    o.x = *reinterpret_cast<unsigned*>(&h0);
    o.y = *reinterpret_cast<unsigned*>(&h1);
    g_xh[idx] = o;
}

// ---------------------------------------------------------------------------
// K3b: convert W -> fp16 combined layout [k][j] (j<64: mu, else logstd); bias
// ---------------------------------------------------------------------------
__global__ void k_wconv(const float* __restrict__ Wmu, const float* __restrict__ bmu,
                        const float* __restrict__ Wls, const float* __restrict__ bls) {
    int i = blockIdx.x * blockDim.x + threadIdx.x;
    if (i < 128 * 128) {
        int k = i >> 7, j = i & 127;
        float w = (j < 64) ? Wmu[k * 64 + j] : Wls[k * 64 + (j - 64)];
        g_wh[i] = __float2half_rn(w);
    }
    if (i < 128) g_bias[i] = (i < 64) ? bmu[i] : bls[i - 64];
}

// ---------------------------------------------------------------------------
// K4: permute edges into dst-sorted order (src index only, 4B records)
// ---------------------------------------------------------------------------
__global__ void k_permute(const int* __restrict__ rowi,
                          const int* __restrict__ coli, int E) {
    int i = blockIdx.x * blockDim.x + threadIdx.x;
    int base = i * 4;
    if (base + 3 < E) {
        int4 s4 = *reinterpret_cast<const int4*>(rowi + base);
        int4 d4 = *reinterpret_cast<const int4*>(coli + base);
        g_edge[g_off[d4.x] + atomicAdd(&g_deg[d4.x], 1)] = s4.x;
        g_edge[g_off[d4.y] + atomicAdd(&g_deg[d4.y], 1)] = s4.y;
        g_edge[g_off[d4.z] + atomicAdd(&g_deg[d4.z], 1)] = s4.z;
        g_edge[g_off[d4.w] + atomicAdd(&g_deg[d4.w], 1)] = s4.w;
    } else if (base < E) {
        for (int e = base; e < E; ++e) {
            int s = rowi[e], d = coli[e];
            g_edge[g_off[d] + atomicAdd(&g_deg[d], 1)] = s;
        }
    }
}

// ---------------------------------------------------------------------------
// K5: gather-aggregate (fp16 rows, fp32 accumulate), fp16 output.
//   acch[v] = fp16( dinv[v] * ( xh[v] + sum_e xh[src_e] ) )
// One warp per dst node; each lane owns 4 features.
// ---------------------------------------------------------------------------
__global__ void k_gather(int n) {
    int gwarp = (blockIdx.x * blockDim.x + threadIdx.x) >> 5;
    int lane  = threadIdx.x & 31;
    if (gwarp >= n) return;
    int v = gwarp;

    float dv_dst = g_dinv[v];
    int offs = g_off[v];
    int cnt  = g_deg[v];

    float ax, ay, az, aw;
    {
        uint2 h = __ldg(&g_xh[(size_t)v * H2_ROW + lane]);
        float2 f0 = __half22float2(*reinterpret_cast<__half2*>(&h.x));
        float2 f1 = __half22float2(*reinterpret_cast<__half2*>(&h.y));
        ax = f0.x; ay = f0.y; az = f1.x; aw = f1.y;
    }

    for (int base = 0; base < cnt; base += 32) {
        int m = min(32, cnt - base);
        int s = 0;
        if (base + lane < cnt) s = __ldg(&g_edge[offs + base + lane]);

        int e = 0;
        for (; e + 3 < m; e += 4) {
            int s0 = __shfl_sync(0xffffffffu, s, e);
            int s1 = __shfl_sync(0xffffffffu, s, e + 1);
            int s2 = __shfl_sync(0xffffffffu, s, e + 2);
            int s3 = __shfl_sync(0xffffffffu, s, e + 3);
            uint2 h0 = __ldg(&g_xh[(size_t)s0 * H2_ROW + lane]);
            uint2 h1 = __ldg(&g_xh[(size_t)s1 * H2_ROW + lane]);
            uint2 h2 = __ldg(&g_xh[(size_t)s2 * H2_ROW + lane]);
            uint2 h3 = __ldg(&g_xh[(size_t)s3 * H2_ROW + lane]);
            float2 a, b;
            a = __half22float2(*reinterpret_cast<__half2*>(&h0.x));
            b = __half22float2(*reinterpret_cast<__half2*>(&h0.y));
            ax += a.x; ay += a.y; az += b.x; aw += b.y;
            a = __half22float2(*reinterpret_cast<__half2*>(&h1.x));
            b = __half22float2(*reinterpret_cast<__half2*>(&h1.y));
            ax += a.x; ay += a.y; az += b.x; aw += b.y;
            a = __half22float2(*reinterpret_cast<__half2*>(&h2.x));
            b = __half22float2(*reinterpret_cast<__half2*>(&h2.y));
            ax += a.x; ay += a.y; az += b.x; aw += b.y;
            a = __half22float2(*reinterpret_cast<__half2*>(&h3.x));
            b = __half22float2(*reinterpret_cast<__half2*>(&h3.y));
            ax += a.x; ay += a.y; az += b.x; aw += b.y;
        }
        for (; e < m; ++e) {
            int s0 = __shfl_sync(0xffffffffu, s, e);
            uint2 h0 = __ldg(&g_xh[(size_t)s0 * H2_ROW + lane]);
            float2 a = __half22float2(*reinterpret_cast<__half2*>(&h0.x));
            float2 b = __half22float2(*reinterpret_cast<__half2*>(&h0.y));
            ax += a.x; ay += a.y; az += b.x; aw += b.y;
        }
    }

    __half2 h0 = __floats2half2_rn(ax * dv_dst, ay * dv_dst);
    __half2 h1 = __floats2half2_rn(az * dv_dst, aw * dv_dst);
    uint2 o;
    o.x = *reinterpret_cast<unsigned*>(&h0);
    o.y = *reinterpret_cast<unsigned*>(&h1);
    g_acch[(size_t)v * H2_ROW + lane] = o;
}

// ---------------------------------------------------------------------------
// K6: HMMA GEMM:  out = g_acch @ g_wh + g_bias   (fp16 in, fp32 accumulate)
// Block: 256 threads (8 warps), 128-row tile, all 128 combined cols.
// Warp w handles rows [16w, 16w+16). mma.sync m16n8k16, 16 n-tiles, 8 k-steps.
// smem: A[128][136] halves + W[128][136] halves + bias (padded stride kills
// ldmatrix bank conflicts).
// ---------------------------------------------------------------------------
__global__ void k_gemm_hmma(float* __restrict__ out, int n) {
    extern __shared__ __half sm[];
    __half* As = sm;                         // 128*136
    __half* Ws = sm + 128 * 136;             // 128*136
    float*  bs = (float*)(sm + 2 * 128 * 136);

    int tid = threadIdx.x;
    int rowbase = blockIdx.x * 128;

    // load W tile (g_wh is [k][j], 16 uint4 per row)
    {
        const uint4* src = reinterpret_cast<const uint4*>(g_wh);
        for (int t = tid; t < 128 * 16; t += 256) {
            int r = t >> 4, c = t & 15;
            *reinterpret_cast<uint4*>(Ws + r * 136 + c * 8) = src[r * 16 + c];
        }
    }
    // load A tile (g_acch rows; rows >= n are zero-init garbage, outputs guarded)
    {
        const uint4* src = reinterpret_cast<const uint4*>(g_acch);
        for (int t = tid; t < 128 * 16; t += 256) {
            int r = t >> 4, c = t & 15;
            *reinterpret_cast<uint4*>(As + r * 136 + c * 8) =
                src[(size_t)(rowbase + r) * 16 + c];
        }
    }
    if (tid < 128) bs[tid] = g_bias[tid];
    __syncthreads();

    int warp = tid >> 5, lane = tid & 31;
    int m0 = warp * 16;

    float c[16][4];
    #pragma unroll
    for (int t = 0; t < 16; ++t) { c[t][0] = c[t][1] = c[t][2] = c[t][3] = 0.f; }

    uint32_t a_base = (uint32_t)__cvta_generic_to_shared(As);
    uint32_t b_base = (uint32_t)__cvta_generic_to_shared(Ws);

    #pragma unroll
    for (int kk = 0; kk < 8; ++kk) {
        int k0 = kk * 16;
        uint32_t a0, a1, a2, a3;
        {
            int r   = m0 + (lane & 15);
            int col = k0 + 8 * (lane >> 4);
            uint32_t addr = a_base + (uint32_t)(r * 136 + col) * 2u;
            asm volatile(
                "ldmatrix.sync.aligned.m8n8.x4.shared.b16 {%0,%1,%2,%3}, [%4];"
                : "=r"(a0), "=r"(a1), "=r"(a2), "=r"(a3) : "r"(addr));
        }
        #pragma unroll
        for (int nt = 0; nt < 16; ++nt) {
            uint32_t b0, b1;
            int r = k0 + (lane & 15);
            uint32_t addr = b_base + (uint32_t)(r * 136 + nt * 8) * 2u;
            asm volatile(
                "ldmatrix.sync.aligned.m8n8.x2.trans.shared.b16 {%0,%1}, [%2];"
                : "=r"(b0), "=r"(b1) : "r"(addr));
            asm volatile(
                "mma.sync.aligned.m16n8k16.row.col.f32.f16.f16.f32 "
                "{%0,%1,%2,%3}, {%4,%5,%6,%7}, {%8,%9}, {%0,%1,%2,%3};"
                : "+f"(c[nt][0]), "+f"(c[nt][1]), "+f"(c[nt][2]), "+f"(c[nt][3])
                : "r"(a0), "r"(a1), "r"(a2), "r"(a3), "r"(b0), "r"(b1));
        }
    }

    // epilogue: bias + split mu/logstd
    int g  = lane >> 2;
    int t4 = lane & 3;
    float* outm = out;
    float* outl = out + (size_t)n * 64;
    #pragma unroll
    for (int nt = 0; nt < 16; ++nt) {
        int col = nt * 8 + t4 * 2;
        float bi0 = bs[col], bi1 = bs[col + 1];
        int v0 = rowbase + m0 + g;
        int v1 = v0 + 8;
        if (col < 64) {
            if (v0 < n)
                *reinterpret_cast<float2*>(outm + (size_t)v0 * 64 + col) =
                    make_float2(c[nt][0] + bi0, c[nt][1] + bi1);
            if (v1 < n)
                *reinterpret_cast<float2*>(outm + (size_t)v1 * 64 + col) =
                    make_float2(c[nt][2] + bi0, c[nt][3] + bi1);
        } else {
            int cl = col - 64;
            if (v0 < n)
                *reinterpret_cast<float2*>(outl + (size_t)v0 * 64 + cl) =
                    make_float2(c[nt][0] + bi0, c[nt][1] + bi1);
            if (v1 < n)
                *reinterpret_cast<float2*>(outl + (size_t)v1 * 64 + cl) =
                    make_float2(c[nt][2] + bi0, c[nt][3] + bi1);
        }
    }
}

// ---------------------------------------------------------------------------
// launch
// ---------------------------------------------------------------------------
extern "C" void kernel_launch(void* const* d_in, const int* in_sizes, int n_in,
                              void* d_out, int out_size) {
    const float* x   = (const float*)d_in[0];
    const int*   ei  = (const int*)d_in[1];
    const float* Wmu = (const float*)d_in[2];
    const float* bmu = (const float*)d_in[3];
    const float* Wls = (const float*)d_in[4];
    const float* bls = (const float*)d_in[5];

    int n = in_sizes[0] / F_IN;     // 100000
    int E = in_sizes[1] / 2;        // 3200000
    const int* rowi = ei;           // edge_index[0] (src)
    const int* coli = ei + E;       // edge_index[1] (dst)

    int nb = (n + SCAN_BLK - 1) / SCAN_BLK;   // 98

    k_zero<<<(n + 255) / 256, 256>>>(n);
    k_count<<<((E + 3) / 4 + 255) / 256, 256>>>(coli, E);
    k_scan_part<<<nb, SCAN_BLK>>>(n);
    k_scan_sums<<<1, 128>>>(nb);
    k_scan_add<<<(n + 255) / 256, 256>>>(n);
    k_prescale<<<(n * F4 + 255) / 256, 256>>>(x, n);
    k_wconv<<<64, 256>>>(Wmu, bmu, Wls, bls);
    k_permute<<<((E + 3) / 4 + 255) / 256, 256>>>(rowi, coli, E);
    k_gather<<<(n * 32 + 255) / 256, 256>>>(n);

    int smem_bytes = 2 * 128 * 136 * (int)sizeof(__half) + 128 * (int)sizeof(float);
    cudaFuncSetAttribute(k_gemm_hmma, cudaFuncAttributeMaxDynamicSharedMemorySize,
                         smem_bytes);
    k_gemm_hmma<<<(n + 127) / 128, 256, smem_bytes>>>((float*)d_out, n);
}